// round 3
// baseline (speedup 1.0000x reference)
#include <cuda_runtime.h>
#include <cuda_bf16.h>
#include <math.h>

#define BB 4
#define CC 64
#define NN 64

typedef unsigned long long ull;

// ---------------------------------------------------------------------------
// Device scratch (no runtime allocation allowed)
// ---------------------------------------------------------------------------
__device__ float2 g_G[BB * NN * 3 * CC * CC];   // 25.2 MB: G[b][v][kh][i][j]
__device__ float  g_part[BB * NN * NN];         // weighted per-frequency logdets

// ---------------------------------------------------------------------------
// f32x2 packed helpers
// ---------------------------------------------------------------------------
__device__ __forceinline__ ull pk2(float lo, float hi) {
    ull r; asm("mov.b64 %0, {%1,%2};" : "=l"(r) : "f"(lo), "f"(hi)); return r;
}
__device__ __forceinline__ void upk2(ull v, float &lo, float &hi) {
    asm("mov.b64 {%0,%1}, %2;" : "=f"(lo), "=f"(hi) : "l"(v));
}
__device__ __forceinline__ ull fma2(ull a, ull b, ull c) {
    ull r; asm("fma.rn.f32x2 %0, %1, %2, %3;" : "=l"(r) : "l"(a), "l"(b), "l"(c));
    return r;
}
__device__ __forceinline__ ull sel4(ull a0, ull a1, ull a2, ull a3, int s) {
    ull x01 = (s & 1) ? a1 : a0;
    ull x23 = (s & 1) ? a3 : a2;
    return (s & 2) ? x23 : x01;
}

// ---------------------------------------------------------------------------
// Kernel 1: G build. G[b,v,kh,i,j] = sum_kw Kfull[b,i,j,kh,kw] * e^{-2pi i v kw/64}
// Identity ('I + net') folded in at (i==j, kh==1, kw==1).
// ---------------------------------------------------------------------------
__global__ __launch_bounds__(256) void gbuild_kernel(const float* __restrict__ K) {
    int v = blockIdx.x & 63;
    int b = blockIdx.x >> 6;
    float th = -6.283185307179586f * (float)v / 64.0f;
    float s1, c1;
    sincosf(th, &s1, &c1);
    float c2 = c1 * c1 - s1 * s1;
    float s2 = 2.0f * s1 * c1;
    long long base = ((long long)(b * 64 + v)) * 3 * 4096;
    for (int e = threadIdx.x; e < 4096; e += 256) {
        int i = e >> 6, j = e & 63;
        const float* kp = K + ((size_t)(b * 64 + i) * 64 + j) * 9;
        float k[9];
#pragma unroll
        for (int t = 0; t < 9; t++) k[t] = kp[t];
        if (i == j) k[4] += 1.0f;
#pragma unroll
        for (int kh = 0; kh < 3; kh++) {
            float re = k[3 * kh] + k[3 * kh + 1] * c1 + k[3 * kh + 2] * c2;
            float im = k[3 * kh + 1] * s1 + k[3 * kh + 2] * s2;
            g_G[base + kh * 4096 + e] = make_float2(re, im);
        }
    }
}

// ---------------------------------------------------------------------------
// Kernel 2: circular conv. CTA per (b,co). Padded input plane in smem.
// ---------------------------------------------------------------------------
__global__ __launch_bounds__(256) void conv_kernel(const float* __restrict__ x,
                                                   const float* __restrict__ K,
                                                   const float* __restrict__ bias,
                                                   float* __restrict__ out) {
    __shared__ float sIn[66 * 68];
    __shared__ float sTap[9];
    int co = blockIdx.x;
    int b  = blockIdx.y;
    int tid = threadIdx.x;
    int ty = tid >> 4, tx = tid & 15;
    int py = ty * 4, px = tx * 4;

    float acc[4][4];
#pragma unroll
    for (int r = 0; r < 4; r++)
#pragma unroll
        for (int c = 0; c < 4; c++) acc[r][c] = 0.0f;

    for (int ci = 0; ci < 64; ci++) {
        __syncthreads();
        const float* xp = x + (size_t)(b * 64 + ci) * 4096;
        for (int e = tid; e < 66 * 66; e += 256) {
            int rr = e / 66;
            int cc2 = e - rr * 66;
            int gy = (rr + 63) & 63;
            int gx = (cc2 + 63) & 63;
            sIn[rr * 68 + cc2] = xp[gy * 64 + gx];
        }
        if (tid < 9) {
            float t = K[((size_t)(b * 64 + co) * 64 + ci) * 9 + tid];
            if (ci == co && tid == 4) t += 1.0f;
            sTap[tid] = t;
        }
        __syncthreads();
        float tp[9];
#pragma unroll
        for (int t = 0; t < 9; t++) tp[t] = sTap[t];
        float patch[6][6];
#pragma unroll
        for (int dr = 0; dr < 6; dr++)
#pragma unroll
            for (int dc = 0; dc < 6; dc++)
                patch[dr][dc] = sIn[(py + dr) * 68 + px + dc];
#pragma unroll
        for (int r = 0; r < 4; r++)
#pragma unroll
            for (int c = 0; c < 4; c++) {
                float a = acc[r][c];
#pragma unroll
                for (int kh = 0; kh < 3; kh++)
#pragma unroll
                    for (int kw = 0; kw < 3; kw++)
                        a = fmaf(tp[kh * 3 + kw], patch[r + kh][c + kw], a);
                acc[r][c] = a;
            }
    }
    float bv = bias[b * 64 + co];
    float* op = out + (size_t)(b * 64 + co) * 4096;
#pragma unroll
    for (int r = 0; r < 4; r++)
#pragma unroll
        for (int c = 0; c < 4; c++)
            op[(py + r) * 64 + px + c] = acc[r][c] + bv;
}

// ---------------------------------------------------------------------------
// Kernel 3: per-frequency complex 64x64 LU with partial pivoting.
// 256 threads; thread (ty,tx) owns a 4x4 complex tile in registers (f32x2).
// Physical row swap via smem broadcast keeps elimination triangular.
// ---------------------------------------------------------------------------
__global__ __launch_bounds__(256) void lu_kernel() {
    int u = blockIdx.x, v = blockIdx.y, b = blockIdx.z;
    int tid = threadIdx.x;
    int ty = tid >> 4, tx = tid & 15;

    int uc = (64 - u) & 63, vc = (64 - v) & 63;
    bool canon = (u < uc) || (u == uc && v <= vc);
    if (!canon) {
        if (tid == 0) g_part[b * 4096 + u * 64 + v] = 0.0f;
        return;
    }
    float weight = (u == uc && v == vc) ? 1.0f : 2.0f;

    __shared__ float4 cand[16];
    __shared__ ull colM[64];
    __shared__ ull rowV[64];   // pivot row (pre-swap row p)
    __shared__ ull rowK[64];   // pre-swap row k
    __shared__ float2 s_cp;
    __shared__ int s_p;

    // ---- build A = sum_kh G[b,v,kh] * wu^kh ----
    const float2* Gb = g_G + (long long)((b * 64 + v) * 3) * 4096;
    float su, cu;
    sincosf(-6.283185307179586f * (float)u / 64.0f, &su, &cu);
    float cu2 = cu * cu - su * su;
    float su2 = 2.0f * su * cu;

    ull acc[4][4];
#pragma unroll
    for (int r = 0; r < 4; r++)
#pragma unroll
        for (int c = 0; c < 4; c++) {
            int e = (4 * ty + r) * 64 + (4 * tx + c);
            float2 g0 = Gb[e];
            float2 g1 = Gb[4096 + e];
            float2 g2 = Gb[8192 + e];
            float re = g0.x + cu * g1.x - su * g1.y + cu2 * g2.x - su2 * g2.y;
            float im = g0.y + cu * g1.y + su * g1.x + cu2 * g2.y + su2 * g2.x;
            acc[r][c] = pk2(re, im);
        }

    float logAcc = 0.0f;   // meaningful on tid 0 only

    for (int tc = 0; tc < 16; tc++) {
#pragma unroll
        for (int kc = 0; kc < 4; kc++) {
            int k = tc * 4 + kc;

            // ---- S1: column owners write pivot candidates; row-k owners stage rowK
            if (tx == tc) {
                float best = -1.0f, bre = 0.0f, bim = 0.0f;
                int bidx = 0;
#pragma unroll
                for (int r = 0; r < 4; r++) {
                    int i = 4 * ty + r;
                    float re, im;
                    upk2(acc[r][kc], re, im);
                    float n2 = re * re + im * im;
                    if (i >= k && n2 > best) { best = n2; bidx = i; bre = re; bim = im; }
                }
                cand[ty] = make_float4(best, __int_as_float(bidx), bre, bim);
            }
            if (ty == tc) {
#pragma unroll
                for (int c = 0; c < 4; c++) rowK[4 * tx + c] = acc[kc][c];
            }
            __syncthreads();

            // ---- S2: warp 0 reduces 16 candidates
            if (tid < 32) {
                float4 cd = (tid < 16) ? cand[tid] : make_float4(-2.0f, 0.0f, 0.0f, 0.0f);
                float bv = cd.x, bre = cd.z, bim = cd.w;
                int bix = __float_as_int(cd.y);
#pragma unroll
                for (int off = 8; off >= 1; off >>= 1) {
                    float ov  = __shfl_xor_sync(0xffffffffu, bv, off);
                    int   oix = __shfl_xor_sync(0xffffffffu, bix, off);
                    float ore = __shfl_xor_sync(0xffffffffu, bre, off);
                    float oim = __shfl_xor_sync(0xffffffffu, bim, off);
                    if (ov > bv || (ov == bv && oix < bix)) { bv = ov; bix = oix; bre = ore; bim = oim; }
                }
                if (tid == 0) {
                    float inv = 1.0f / bv;           // bv = |pivot|^2
                    s_cp = make_float2(bre * inv, -bim * inv);
                    s_p = bix;
                    logAcc += 0.5f * logf(bv);
                }
            }
            __syncthreads();

            // ---- S3: swap rows k<->p; compute multipliers
            int p = s_p;
            float2 cp = s_cp;
            if (ty == (p >> 2)) {
                int pl = p & 3;
#pragma unroll
                for (int c = 0; c < 4; c++) {
                    ull val = sel4(acc[0][c], acc[1][c], acc[2][c], acc[3][c], pl);
                    rowV[4 * tx + c] = val;
                }
#pragma unroll
                for (int c = 0; c < 4; c++) {
                    ull nv = rowK[4 * tx + c];
                    acc[0][c] = (pl == 0) ? nv : acc[0][c];
                    acc[1][c] = (pl == 1) ? nv : acc[1][c];
                    acc[2][c] = (pl == 2) ? nv : acc[2][c];
                    acc[3][c] = (pl == 3) ? nv : acc[3][c];
                }
            }
            if (tx == tc) {
#pragma unroll
                for (int r = 0; r < 4; r++) {
                    int i = 4 * ty + r;
                    if (i > k) {
                        float re, im;
                        upk2(acc[r][kc], re, im);
                        float mr = re * cp.x - im * cp.y;
                        float mi = re * cp.y + im * cp.x;
                        colM[i] = pk2(mr, mi);
                    }
                }
            }
            __syncthreads();

            // ---- S4: rank-1 update (warp-uniform row guard)
            if (4 * (ty | 1) + 3 > k) {
                ull rv[4], rs[4];
#pragma unroll
                for (int c = 0; c < 4; c++) {
                    rv[c] = rowV[4 * tx + c];
                    float br, bi;
                    upk2(rv[c], br, bi);
                    rs[c] = pk2(bi, -br);
                }
#pragma unroll
                for (int r = 0; r < 4; r++) {
                    int i = 4 * ty + r;
                    ull mm = (i > k) ? colM[i] : 0ull;
                    float mr, mi;
                    upk2(mm, mr, mi);
                    ull mrd = pk2(-mr, -mr);
                    ull mid = pk2(mi, mi);
#pragma unroll
                    for (int c = 0; c < 4; c++) {
                        acc[r][c] = fma2(mrd, rv[c], acc[r][c]);
                        acc[r][c] = fma2(mid, rs[c], acc[r][c]);
                    }
                }
            }
        }
    }

    if (tid == 0) g_part[b * 4096 + u * 64 + v] = weight * logAcc;
}

// ---------------------------------------------------------------------------
// Kernel 4: reduce per-frequency partials -> logdet[b]
// ---------------------------------------------------------------------------
__global__ __launch_bounds__(256) void reduce_kernel(float* __restrict__ out) {
    __shared__ double red[256];
    int b = blockIdx.x;
    double s = 0.0;
    for (int e = threadIdx.x; e < 4096; e += 256)
        s += (double)g_part[b * 4096 + e];
    red[threadIdx.x] = s;
    __syncthreads();
    for (int st = 128; st > 0; st >>= 1) {
        if (threadIdx.x < st) red[threadIdx.x] += red[threadIdx.x + st];
        __syncthreads();
    }
    if (threadIdx.x == 0) out[1048576 + b] = (float)red[0];
}

// ---------------------------------------------------------------------------
extern "C" void kernel_launch(void* const* d_in, const int* in_sizes, int n_in,
                              void* d_out, int out_size) {
    const float* x = nullptr;
    const float* K = nullptr;
    const float* bias = nullptr;
    for (int i = 0; i < n_in; i++) {
        if (in_sizes[i] == 1048576)      x    = (const float*)d_in[i];
        else if (in_sizes[i] == 147456)  K    = (const float*)d_in[i];
        else if (in_sizes[i] == 256)     bias = (const float*)d_in[i];
    }
    float* out = (float*)d_out;

    gbuild_kernel<<<256, 256>>>(K);
    conv_kernel<<<dim3(64, 4), 256>>>(x, K, bias, out);
    lu_kernel<<<dim3(64, 64, 4), 256>>>();
    reduce_kernel<<<4, 256>>>(out);
}